// round 1
// baseline (speedup 1.0000x reference)
#include <cuda_runtime.h>

// Sobel magnitude: out = sqrt(gx^2 + gy^2 + 1e-4), 3x3 cross-correlation,
// zero padding, x: [64, 1, 512, 512] fp32.
// kx = [[1,0,-1],[2,0,-2],[1,0,-1]]/4 ; ky = [[1,2,1],[0,0,0],[-1,-2,-1]]/4

#define W 512
#define H 512
#define EPS 1e-4f

// Each thread produces 4 horizontally-adjacent outputs (one float4 store).
// blockDim = (32, 8): 32 threads * 4 px = 128 px wide, 8 rows tall per CTA.
__global__ __launch_bounds__(256) void sobel_kernel(
    const float* __restrict__ in, float* __restrict__ out)
{
    const int ox = (blockIdx.x * 32 + threadIdx.x) * 4;   // 0..508, float4 aligned
    const int oy = blockIdx.y * 8 + threadIdx.y;          // 0..511
    const long long img = (long long)blockIdx.z * (W * H);

    const float* base = in + img;

    // v[r][0..5] = cols ox-1 .. ox+4 of row oy-1+r (zero outside image)
    float v[3][6];

    #pragma unroll
    for (int r = 0; r < 3; ++r) {
        const int y = oy - 1 + r;
        if (y >= 0 && y < H) {
            const float* row = base + (long long)y * W;
            const float4 c = *reinterpret_cast<const float4*>(row + ox);
            v[r][1] = c.x; v[r][2] = c.y; v[r][3] = c.z; v[r][4] = c.w;
            v[r][0] = (ox > 0)       ? __ldg(row + ox - 1) : 0.0f;
            v[r][5] = (ox + 4 < W)   ? __ldg(row + ox + 4) : 0.0f;
        } else {
            #pragma unroll
            for (int j = 0; j < 6; ++j) v[r][j] = 0.0f;
        }
    }

    float4 o;
    float* op = reinterpret_cast<float*>(&o);
    #pragma unroll
    for (int k = 0; k < 4; ++k) {
        // columns k, k+1, k+2 of the 6-wide window
        const float gx = 0.25f * ( (v[0][k] - v[0][k + 2])
                         + 2.0f *  (v[1][k] - v[1][k + 2])
                         +         (v[2][k] - v[2][k + 2]) );
        const float gy = 0.25f * ( (v[0][k] + 2.0f * v[0][k + 1] + v[0][k + 2])
                         -         (v[2][k] + 2.0f * v[2][k + 1] + v[2][k + 2]) );
        op[k] = sqrtf(fmaf(gx, gx, fmaf(gy, gy, EPS)));
    }

    *reinterpret_cast<float4*>(out + img + (long long)oy * W + ox) = o;
}

extern "C" void kernel_launch(void* const* d_in, const int* in_sizes, int n_in,
                              void* d_out, int out_size)
{
    const float* x = (const float*)d_in[0];
    float* out = (float*)d_out;

    dim3 block(32, 8, 1);                 // 256 threads
    dim3 grid(W / (32 * 4), H / 8, 64);   // 4 x 64 x 64
    sobel_kernel<<<grid, block>>>(x, out);
}